// round 1
// baseline (speedup 1.0000x reference)
#include <cuda_runtime.h>
#include <cstdio>

#define Bq 512
#define Wq 50
#define Tq 50
#define Hq 1024
#define Vq 1024
#define MVq 64
#define Lq 30
#define H4 4096
#define EOS_IDX 1

// ---------------- device scratch (static, no allocation) ----------------
__device__ float g_aw[Bq * Wq];
__device__ float g_r[Bq * Hq];
__device__ float g_h[Bq * Hq];
__device__ float g_c[Bq * Hq];
__device__ float g_g[Bq * H4];
__device__ float g_msg[Lq * Bq * MVq];
__device__ float g_msgmask[Lq * Bq];
__device__ float g_m[Bq];
__device__ float g_vec[H4];
__device__ float g_cterm[1];
__device__ float g_menc_xterm[(size_t)Lq * Bq * H4];   // 251 MB
__device__ float g_dec_xterm[(size_t)Tq * Bq * H4];    // 419 MB
__device__ float g_dec_in[(size_t)Tq * Bq * Hq];       // 105 MB

__device__ __forceinline__ float sigf(float x) { return 1.f / (1.f + expf(-x)); }

// ---------------- generic SGEMM: C = A(MxK) @ W(NxK)^T [+bias(N)] [+addM(MxN)] ----------
// M % 64 == 0, N % 64 == 0, K % 16 == 0 (all call sites satisfy this)
#define BM 64
#define BN 64
#define BK 16
__global__ __launch_bounds__(256) void sgemm_kernel(
    const float* __restrict__ A, const float* __restrict__ Wt,
    float* __restrict__ C, int M, int N, int K,
    const float* __restrict__ bias, const float* __restrict__ addM)
{
    __shared__ float As[BK][BM + 4];
    __shared__ float Bs[BK][BN + 4];
    const int tid = threadIdx.x;
    const int tx = tid & 15, ty = tid >> 4;
    const int bm = blockIdx.y * BM;
    const int bn = blockIdx.x * BN;
    const int lrow = tid >> 2;          // 0..63
    const int lcol = (tid & 3) * 4;     // 0,4,8,12

    float acc[4][4] = {};

    for (int k0 = 0; k0 < K; k0 += BK) {
        float4 av = *(const float4*)(A + (size_t)(bm + lrow) * K + k0 + lcol);
        As[lcol + 0][lrow] = av.x;
        As[lcol + 1][lrow] = av.y;
        As[lcol + 2][lrow] = av.z;
        As[lcol + 3][lrow] = av.w;
        float4 bv = *(const float4*)(Wt + (size_t)(bn + lrow) * K + k0 + lcol);
        Bs[lcol + 0][lrow] = bv.x;
        Bs[lcol + 1][lrow] = bv.y;
        Bs[lcol + 2][lrow] = bv.z;
        Bs[lcol + 3][lrow] = bv.w;
        __syncthreads();
#pragma unroll
        for (int k = 0; k < BK; k++) {
            float4 af = *(const float4*)&As[k][ty * 4];
            float4 bf = *(const float4*)&Bs[k][tx * 4];
            float a[4] = {af.x, af.y, af.z, af.w};
            float b[4] = {bf.x, bf.y, bf.z, bf.w};
#pragma unroll
            for (int i = 0; i < 4; i++)
#pragma unroll
                for (int j = 0; j < 4; j++)
                    acc[i][j] += a[i] * b[j];
        }
        __syncthreads();
    }

#pragma unroll
    for (int i = 0; i < 4; i++) {
        int row = bm + ty * 4 + i;
#pragma unroll
        for (int j = 0; j < 4; j++) {
            int col = bn + tx * 4 + j;
            float v = acc[i][j];
            if (bias) v += bias[col];
            if (addM) v += addM[(size_t)row * N + col];
            C[(size_t)row * N + col] = v;
        }
    }
}

// ---------------- attention const term: dot(set_h0, attn_w[0:H]) + attn_b --------------
__global__ void cterm_kernel(const float* __restrict__ set_h0,
                             const float* __restrict__ attn_w,
                             const float* __restrict__ attn_b)
{
    __shared__ float red[256];
    float s = 0.f;
    for (int i = threadIdx.x; i < Hq; i += 256) s += set_h0[i] * attn_w[i];
    red[threadIdx.x] = s;
    __syncthreads();
    for (int st = 128; st; st >>= 1) {
        if (threadIdx.x < st) red[threadIdx.x] += red[threadIdx.x + st];
        __syncthreads();
    }
    if (threadIdx.x == 0) g_cterm[0] = red[0] + attn_b[0];
}

// ---------------- attention weights aw[b,w] -------------------------------------------
__global__ void aw_kernel(const int* __restrict__ input_var,
                          const float* __restrict__ input_mask,
                          const float* __restrict__ embedding,
                          const float* __restrict__ attn_w)
{
    int gw = (blockIdx.x * blockDim.x + threadIdx.x) >> 5;
    int lane = threadIdx.x & 31;
    if (gw >= Bq * Wq) return;
    int b = gw / Wq, w = gw % Wq;
    int idx = input_var[b * Wq + w];
    const float* e = embedding + (size_t)idx * Hq;
    const float* a2 = attn_w + Hq;
    float s = 0.f;
    for (int k = lane; k < Hq; k += 32) s += e[k] * a2[k];
#pragma unroll
    for (int o = 16; o; o >>= 1) s += __shfl_xor_sync(0xffffffffu, s, o);
    if (lane == 0) {
        float z = sigf(s + g_cterm[0]);
        g_aw[b * Wq + w] = z * input_mask[w * Bq + b];
    }
}

// ---------------- r[b,h] = sum_w aw[b,w] * embedding[iv[b,w], h] -----------------------
__global__ void r_kernel(const int* __restrict__ input_var,
                         const float* __restrict__ embedding)
{
    int b = blockIdx.x;
    __shared__ float awr[Wq];
    __shared__ int idxs[Wq];
    if (threadIdx.x < Wq) {
        awr[threadIdx.x] = g_aw[b * Wq + threadIdx.x];
        idxs[threadIdx.x] = input_var[b * Wq + threadIdx.x];
    }
    __syncthreads();
    for (int h = threadIdx.x; h < Hq; h += blockDim.x) {
        float acc = 0.f;
#pragma unroll 5
        for (int w = 0; w < Wq; w++)
            acc += awr[w] * embedding[(size_t)idxs[w] * Hq + h];
        g_r[b * Hq + h] = acc;
    }
}

// ---------------- out[n] = b1[n]+b2[n]+dot(x[K], Wm[n,:]) -------------------------------
__global__ void vecgate_kernel(const float* __restrict__ x, const float* __restrict__ Wm,
                               const float* __restrict__ b1, const float* __restrict__ b2,
                               int K)
{
    int n = (blockIdx.x * blockDim.x + threadIdx.x) >> 5;
    int lane = threadIdx.x & 31;
    if (n >= H4) return;
    float s = 0.f;
    for (int k = lane; k < K; k += 32) s += x[k] * Wm[(size_t)n * K + k];
#pragma unroll
    for (int o = 16; o; o >>= 1) s += __shfl_xor_sync(0xffffffffu, s, o);
    if (lane == 0) g_vec[n] = s + b1[n] + b2[n];
}

// ---------------- broadcast row src[H] into dst[B,H] -----------------------------------
__global__ void bcast_kernel(float* __restrict__ dst, const float* __restrict__ src)
{
    int i = blockIdx.x * blockDim.x + threadIdx.x;
    if (i < Bq * Hq) dst[i] = src[i % Hq];
}

__global__ void ones_kernel()
{
    int i = blockIdx.x * blockDim.x + threadIdx.x;
    if (i < Bq) g_m[i] = 1.f;
}

// ---------------- LSTM pointwise: consumes g_g, updates h,c (optional mask blend) ------
__global__ void lstm_pw_kernel(float* __restrict__ h, float* __restrict__ c,
                               const float* __restrict__ mask)
{
    int i = blockIdx.x * blockDim.x + threadIdx.x;
    if (i >= Bq * Hq) return;
    int b = i / Hq, hh = i % Hq;
    const float* gr = g_g + (size_t)b * H4;
    float gi = gr[hh], gf = gr[Hq + hh], gg = gr[2 * Hq + hh], go = gr[3 * Hq + hh];
    float co = c[i];
    float cn = sigf(gf) * co + sigf(gi) * tanhf(gg);
    float hn = sigf(go) * tanhf(cn);
    if (mask) {
        float mt = mask[b];
        float ho = h[i];
        hn = mt * hn + (1.f - mt) * ho;
        cn = mt * cn + (1.f - mt) * co;
    }
    h[i] = hn;
    c[i] = cn;
}

// ---------------- generator head: probs = softmax(h@outW^T + outb), mask update --------
__global__ void gen_out_kernel(const float* __restrict__ outW,
                               const float* __restrict__ outb, int l)
{
    int b = blockIdx.x;
    int n = threadIdx.x;  // 64 threads
    __shared__ float hs[Hq];
    __shared__ float es[MVq];
    for (int i = n; i < Hq; i += MVq) hs[i] = g_h[b * Hq + i];
    __syncthreads();
    float acc = outb[n];
    const float4* wr = (const float4*)(outW + (size_t)n * Hq);
    const float4* hv = (const float4*)hs;
#pragma unroll 8
    for (int k = 0; k < Hq / 4; k++) {
        float4 w4 = wr[k];
        float4 h4 = hv[k];
        acc += w4.x * h4.x + w4.y * h4.y + w4.z * h4.z + w4.w * h4.w;
    }
    es[n] = acc;
    __syncthreads();
    float mx = -1e30f;
#pragma unroll
    for (int i = 0; i < MVq; i++) mx = fmaxf(mx, es[i]);
    float e = expf(acc - mx);
    __syncthreads();
    es[n] = e;
    __syncthreads();
    float ssum = 0.f;
#pragma unroll
    for (int i = 0; i < MVq; i++) ssum += es[i];
    float p = e / ssum;
    g_msg[(size_t)l * Bq * MVq + b * MVq + n] = p;
    if (n == 0) {
        float mo = g_m[b];
        g_msgmask[l * Bq + b] = mo;
        g_m[b] = mo * (1.f - es[EOS_IDX] / ssum);
    }
}

// ---------------- decoder input gather --------------------------------------------------
__global__ void decin_kernel(const int* __restrict__ target_var,
                             const float* __restrict__ embedding)
{
    long i = (long)blockIdx.x * blockDim.x + threadIdx.x;
    if (i >= (long)Tq * Bq * Hq) return;
    int hh = (int)(i % Hq);
    long tb = i / Hq;
    int b = (int)(tb % Bq);
    int t = (int)(tb / Bq);
    int idx = (t == 0) ? 0 : target_var[(t - 1) * Bq + b];  // SOS_INDEX = 0
    g_dec_in[i] = embedding[(size_t)idx * Hq + hh];
}

// ---------------- host orchestration ----------------------------------------------------
static inline void launch_gemm(const float* A, const float* Wt, float* C,
                               int M, int N, int K,
                               const float* bias, const float* addM)
{
    dim3 grid(N / BN, M / BM);
    sgemm_kernel<<<grid, 256>>>(A, Wt, C, M, N, K, bias, addM);
}

extern "C" void kernel_launch(void* const* d_in, const int* in_sizes, int n_in,
                              void* d_out, int out_size)
{
    // ----- inputs (robust to presence/absence of target_max_len scalar) -----
    int k = 0;
    const int*   input_var  = (const int*)d_in[k++];
    const float* input_mask = (const float*)d_in[k++];
    const int*   target_var = (const int*)d_in[k++];
    if (n_in >= 32) k++;  // skip target_max_len scalar if present
    const float* embedding = (const float*)d_in[k++];
    const float* attn_w    = (const float*)d_in[k++];
    const float* attn_b    = (const float*)d_in[k++];
    const float* set_Wih   = (const float*)d_in[k++];
    const float* set_Whh   = (const float*)d_in[k++];
    const float* set_bih   = (const float*)d_in[k++];
    const float* set_bhh   = (const float*)d_in[k++];
    const float* set_h0    = (const float*)d_in[k++];
    const float* set_c0    = (const float*)d_in[k++];
    const float* gen_x0    = (const float*)d_in[k++];
    const float* gen_Wih   = (const float*)d_in[k++];
    const float* gen_Whh   = (const float*)d_in[k++];
    const float* gen_bih   = (const float*)d_in[k++];
    const float* gen_bhh   = (const float*)d_in[k++];
    const float* gen_outW  = (const float*)d_in[k++];
    const float* gen_outb  = (const float*)d_in[k++];
    const float* menc_Wih  = (const float*)d_in[k++];
    const float* menc_Whh  = (const float*)d_in[k++];
    const float* menc_bih  = (const float*)d_in[k++];
    const float* menc_bhh  = (const float*)d_in[k++];
    const float* menc_h0   = (const float*)d_in[k++];
    const float* menc_c0   = (const float*)d_in[k++];
    const float* dec_Wih   = (const float*)d_in[k++];
    const float* dec_Whh   = (const float*)d_in[k++];
    const float* dec_bih   = (const float*)d_in[k++];
    const float* dec_bhh   = (const float*)d_in[k++];
    const float* dec_outW  = (const float*)d_in[k++];
    const float* dec_outb  = (const float*)d_in[k++];
    float* out = (float*)d_out;

    // ----- device scratch addresses -----
    float *p_r, *p_h, *p_c, *p_g, *p_msg, *p_mm, *p_vec, *p_mx, *p_dx, *p_di;
    cudaGetSymbolAddress((void**)&p_r,   g_r);
    cudaGetSymbolAddress((void**)&p_h,   g_h);
    cudaGetSymbolAddress((void**)&p_c,   g_c);
    cudaGetSymbolAddress((void**)&p_g,   g_g);
    cudaGetSymbolAddress((void**)&p_msg, g_msg);
    cudaGetSymbolAddress((void**)&p_mm,  g_msgmask);
    cudaGetSymbolAddress((void**)&p_vec, g_vec);
    cudaGetSymbolAddress((void**)&p_mx,  g_menc_xterm);
    cudaGetSymbolAddress((void**)&p_dx,  g_dec_xterm);
    cudaGetSymbolAddress((void**)&p_di,  g_dec_in);

    const int BH = Bq * Hq;

    // ===== encoder (set attention + 1 LSTM cell) =====
    cterm_kernel<<<1, 256>>>(set_h0, attn_w, attn_b);
    aw_kernel<<<(Bq * Wq * 32 + 255) / 256, 256>>>(input_var, input_mask, embedding, attn_w);
    r_kernel<<<Bq, 256>>>(input_var, embedding);
    // v_set[n] = set_bih + set_bhh + dot(set_h0, set_Whh[n,:])
    vecgate_kernel<<<(H4 * 32 + 255) / 256, 256>>>(set_h0, set_Whh, set_bih, set_bhh, Hq);
    launch_gemm(p_r, set_Wih, p_g, Bq, H4, Hq, p_vec, nullptr);
    bcast_kernel<<<(BH + 255) / 256, 256>>>(p_c, set_c0);
    lstm_pw_kernel<<<(BH + 255) / 256, 256>>>(p_h, p_c, nullptr);

    // ===== generator scan (L steps) =====
    // xv[n] = gen_bih + gen_bhh + dot(gen_x0, gen_Wih[n,:])  (constant across steps)
    vecgate_kernel<<<(H4 * 32 + 255) / 256, 256>>>(gen_x0, gen_Wih, gen_bih, gen_bhh, MVq);
    ones_kernel<<<(Bq + 255) / 256, 256>>>();
    for (int l = 0; l < Lq; l++) {
        launch_gemm(p_h, gen_Whh, p_g, Bq, H4, Hq, p_vec, nullptr);
        lstm_pw_kernel<<<(BH + 255) / 256, 256>>>(p_h, p_c, nullptr);
        gen_out_kernel<<<Bq, MVq>>>(gen_outW, gen_outb, l);
    }

    // ===== message encoder: hoisted x-term GEMM, then masked scan =====
    launch_gemm(p_msg, menc_Wih, p_mx, Lq * Bq, H4, MVq, menc_bih, nullptr);
    bcast_kernel<<<(BH + 255) / 256, 256>>>(p_h, menc_h0);
    bcast_kernel<<<(BH + 255) / 256, 256>>>(p_c, menc_c0);
    for (int l = 0; l < Lq; l++) {
        launch_gemm(p_h, menc_Whh, p_g, Bq, H4, Hq, menc_bhh,
                    p_mx + (size_t)l * Bq * H4);
        lstm_pw_kernel<<<(BH + 255) / 256, 256>>>(p_h, p_c, p_mm + (size_t)l * Bq);
    }

    // ===== decoder: hoisted input gather + x-term GEMM, then scan with logits =====
    decin_kernel<<<(int)(((long)Tq * Bq * Hq + 255) / 256), 256>>>(target_var, embedding);
    launch_gemm(p_di, dec_Wih, p_dx, Tq * Bq, H4, Hq, dec_bih, nullptr);
    for (int t = 0; t < Tq; t++) {
        launch_gemm(p_h, dec_Whh, p_g, Bq, H4, Hq, dec_bhh,
                    p_dx + (size_t)t * Bq * H4);
        lstm_pw_kernel<<<(BH + 255) / 256, 256>>>(p_h, p_c, nullptr);
        launch_gemm(p_h, dec_outW, out + (size_t)t * Bq * Vq, Bq, Vq, Hq,
                    dec_outb, nullptr);
    }
}

// round 2
// speedup vs baseline: 2.3018x; 2.3018x over previous
#include <cuda_runtime.h>
#include <cstdio>

#define Bq 512
#define Wq 50
#define Tq 50
#define Hq 1024
#define Vq 1024
#define MVq 64
#define Lq 30
#define H4 4096
#define EOS_IDX 1

// ---------------- device scratch (static, no allocation) ----------------
__device__ float g_aw[Bq * Wq];
__device__ float g_r[Bq * Hq];
__device__ float g_h[Bq * Hq];
__device__ float g_c[Bq * Hq];
__device__ float g_g[Bq * H4];
__device__ float g_msg[Lq * Bq * MVq];
__device__ float g_msgmask[Lq * Bq];
__device__ float g_m[Bq];
__device__ float g_vec[H4];
__device__ float g_cterm[1];
__device__ float g_menc_xterm[(size_t)Lq * Bq * H4];   // 251 MB
__device__ float g_dec_xterm[(size_t)Tq * Bq * H4];    // 419 MB
__device__ float g_dec_in[(size_t)Tq * Bq * Hq];       // 105 MB
__device__ float g_decW[(size_t)(H4 + Vq) * Hq];       // 20 MB combined [Whh;outW]
__device__ float g_decb[H4 + Vq];

__device__ __forceinline__ float sigf(float x) { return 1.f / (1.f + expf(-x)); }

__device__ __forceinline__ unsigned f2tf32(float x) {
    unsigned r;
    asm("cvt.rna.tf32.f32 %0, %1;" : "=r"(r) : "f"(x));
    return r;
}

// =====================================================================
// TF32 tensor-core GEMM: C = A(MxK) @ W(NxK)^T [+bias] [+addM (col<addN)]
// Output split: col < colSplit -> C (ld ldC); else -> C2 (ld ldC2).
// Block tile 128x128, K-tile 16, 256 threads (8 warps, 4x2 warp grid,
// warp tile 32x64 = 2x8 m16n8k8 mma tiles).
// Requires: M%128==0, N%128==0, K%16==0, colSplit & addN even.
// =====================================================================
__global__ __launch_bounds__(256, 2) void mma_gemm_kernel(
    const float* __restrict__ A, const float* __restrict__ W,
    float* __restrict__ C, float* __restrict__ C2,
    int M, int N, int K,
    const float* __restrict__ bias, const float* __restrict__ addM,
    int addN, int colSplit, int ldC, int ldC2)
{
    __shared__ unsigned As[128][20];  // [m][k], stride 20 -> conflict-free frag loads
    __shared__ unsigned Bs[128][20];  // [n][k]

    const int tid  = threadIdx.x;
    const int lane = tid & 31;
    const int warp = tid >> 5;
    const int wm   = warp & 3;    // warp m offset = wm*32
    const int wn   = warp >> 2;   // warp n offset = wn*64
    const int gid  = lane >> 2;
    const int tig  = lane & 3;

    const int bm = blockIdx.y * 128;
    const int bn = blockIdx.x * 128;

    // global->smem mapping: 128x16 tile, 256 threads, 2 float4 each
    const int lr = tid >> 2;          // 0..63
    const int lc = (tid & 3) << 2;    // 0,4,8,12

    const float* Ag0 = A + (size_t)(bm + lr) * K + lc;
    const float* Ag1 = A + (size_t)(bm + lr + 64) * K + lc;
    const float* Wg0 = W + (size_t)(bn + lr) * K + lc;
    const float* Wg1 = W + (size_t)(bn + lr + 64) * K + lc;

    float4 fa0 = *(const float4*)Ag0;
    float4 fa1 = *(const float4*)Ag1;
    float4 fb0 = *(const float4*)Wg0;
    float4 fb1 = *(const float4*)Wg1;

    float c[2][8][4];
#pragma unroll
    for (int i = 0; i < 2; i++)
#pragma unroll
        for (int j = 0; j < 8; j++)
#pragma unroll
            for (int q = 0; q < 4; q++) c[i][j][q] = 0.f;

    for (int k0 = 0; k0 < K; k0 += 16) {
        if (k0) __syncthreads();  // previous compute finished before overwrite
        {
            uint4 u;
            u.x = f2tf32(fa0.x); u.y = f2tf32(fa0.y); u.z = f2tf32(fa0.z); u.w = f2tf32(fa0.w);
            *(uint4*)&As[lr][lc] = u;
            u.x = f2tf32(fa1.x); u.y = f2tf32(fa1.y); u.z = f2tf32(fa1.z); u.w = f2tf32(fa1.w);
            *(uint4*)&As[lr + 64][lc] = u;
            u.x = f2tf32(fb0.x); u.y = f2tf32(fb0.y); u.z = f2tf32(fb0.z); u.w = f2tf32(fb0.w);
            *(uint4*)&Bs[lr][lc] = u;
            u.x = f2tf32(fb1.x); u.y = f2tf32(fb1.y); u.z = f2tf32(fb1.z); u.w = f2tf32(fb1.w);
            *(uint4*)&Bs[lr + 64][lc] = u;
        }
        __syncthreads();

        if (k0 + 16 < K) {  // prefetch next K-tile (overlaps with compute below)
            fa0 = *(const float4*)(Ag0 + k0 + 16);
            fa1 = *(const float4*)(Ag1 + k0 + 16);
            fb0 = *(const float4*)(Wg0 + k0 + 16);
            fb1 = *(const float4*)(Wg1 + k0 + 16);
        }

#pragma unroll
        for (int kk = 0; kk < 16; kk += 8) {
            unsigned a[2][4], b[8][2];
#pragma unroll
            for (int mt = 0; mt < 2; mt++) {
                int rm = wm * 32 + mt * 16 + gid;
                a[mt][0] = As[rm][kk + tig];
                a[mt][1] = As[rm + 8][kk + tig];
                a[mt][2] = As[rm][kk + tig + 4];
                a[mt][3] = As[rm + 8][kk + tig + 4];
            }
#pragma unroll
            for (int nt = 0; nt < 8; nt++) {
                int rn = wn * 64 + nt * 8 + gid;
                b[nt][0] = Bs[rn][kk + tig];
                b[nt][1] = Bs[rn][kk + tig + 4];
            }
#pragma unroll
            for (int mt = 0; mt < 2; mt++)
#pragma unroll
                for (int nt = 0; nt < 8; nt++) {
                    asm volatile(
                        "mma.sync.aligned.m16n8k8.row.col.f32.tf32.tf32.f32 "
                        "{%0,%1,%2,%3}, {%4,%5,%6,%7}, {%8,%9}, {%0,%1,%2,%3};\n"
                        : "+f"(c[mt][nt][0]), "+f"(c[mt][nt][1]),
                          "+f"(c[mt][nt][2]), "+f"(c[mt][nt][3])
                        : "r"(a[mt][0]), "r"(a[mt][1]), "r"(a[mt][2]), "r"(a[mt][3]),
                          "r"(b[nt][0]), "r"(b[nt][1]));
                }
        }
    }

    // ---------------- epilogue ----------------
#pragma unroll
    for (int mt = 0; mt < 2; mt++) {
#pragma unroll
        for (int nt = 0; nt < 8; nt++) {
            int row = bm + wm * 32 + mt * 16 + gid;
            int col = bn + wn * 64 + nt * 8 + tig * 2;
#pragma unroll
            for (int half = 0; half < 2; half++) {
                int r = row + half * 8;
                float2 v;
                v.x = c[mt][nt][half * 2];
                v.y = c[mt][nt][half * 2 + 1];
                if (bias) { v.x += bias[col]; v.y += bias[col + 1]; }
                if (addM && col < addN) {
                    float2 m = *(const float2*)&addM[(size_t)r * addN + col];
                    v.x += m.x; v.y += m.y;
                }
                if (col < colSplit)
                    *(float2*)&C[(size_t)r * ldC + col] = v;
                else
                    *(float2*)&C2[(size_t)r * ldC2 + (col - colSplit)] = v;
            }
        }
    }
}

// ---------------- attention const term ------------------------------------------------
__global__ void cterm_kernel(const float* __restrict__ set_h0,
                             const float* __restrict__ attn_w,
                             const float* __restrict__ attn_b)
{
    __shared__ float red[256];
    float s = 0.f;
    for (int i = threadIdx.x; i < Hq; i += 256) s += set_h0[i] * attn_w[i];
    red[threadIdx.x] = s;
    __syncthreads();
    for (int st = 128; st; st >>= 1) {
        if (threadIdx.x < st) red[threadIdx.x] += red[threadIdx.x + st];
        __syncthreads();
    }
    if (threadIdx.x == 0) g_cterm[0] = red[0] + attn_b[0];
}

// ---------------- attention weights aw[b,w] -------------------------------------------
__global__ void aw_kernel(const int* __restrict__ input_var,
                          const float* __restrict__ input_mask,
                          const float* __restrict__ embedding,
                          const float* __restrict__ attn_w)
{
    int gw = (blockIdx.x * blockDim.x + threadIdx.x) >> 5;
    int lane = threadIdx.x & 31;
    if (gw >= Bq * Wq) return;
    int b = gw / Wq, w = gw % Wq;
    int idx = input_var[b * Wq + w];
    const float* e = embedding + (size_t)idx * Hq;
    const float* a2 = attn_w + Hq;
    float s = 0.f;
    for (int k = lane; k < Hq; k += 32) s += e[k] * a2[k];
#pragma unroll
    for (int o = 16; o; o >>= 1) s += __shfl_xor_sync(0xffffffffu, s, o);
    if (lane == 0) {
        float z = sigf(s + g_cterm[0]);
        g_aw[b * Wq + w] = z * input_mask[w * Bq + b];
    }
}

// ---------------- r[b,h] = sum_w aw[b,w] * embedding[iv[b,w], h] -----------------------
__global__ void r_kernel(const int* __restrict__ input_var,
                         const float* __restrict__ embedding)
{
    int b = blockIdx.x;
    __shared__ float awr[Wq];
    __shared__ int idxs[Wq];
    if (threadIdx.x < Wq) {
        awr[threadIdx.x] = g_aw[b * Wq + threadIdx.x];
        idxs[threadIdx.x] = input_var[b * Wq + threadIdx.x];
    }
    __syncthreads();
    for (int h = threadIdx.x; h < Hq; h += blockDim.x) {
        float acc = 0.f;
#pragma unroll 5
        for (int w = 0; w < Wq; w++)
            acc += awr[w] * embedding[(size_t)idxs[w] * Hq + h];
        g_r[b * Hq + h] = acc;
    }
}

// ---------------- out[n] = b1[n]+b2[n]+dot(x[K], Wm[n,:]) -------------------------------
__global__ void vecgate_kernel(const float* __restrict__ x, const float* __restrict__ Wm,
                               const float* __restrict__ b1, const float* __restrict__ b2,
                               int K)
{
    int n = (blockIdx.x * blockDim.x + threadIdx.x) >> 5;
    int lane = threadIdx.x & 31;
    if (n >= H4) return;
    float s = 0.f;
    for (int k = lane; k < K; k += 32) s += x[k] * Wm[(size_t)n * K + k];
#pragma unroll
    for (int o = 16; o; o >>= 1) s += __shfl_xor_sync(0xffffffffu, s, o);
    if (lane == 0) g_vec[n] = s + b1[n] + b2[n];
}

// ---------------- broadcast row src[H] into dst[B,H] -----------------------------------
__global__ void bcast_kernel(float* __restrict__ dst, const float* __restrict__ src)
{
    int i = blockIdx.x * blockDim.x + threadIdx.x;
    if (i < Bq * Hq) dst[i] = src[i % Hq];
}

__global__ void ones_kernel()
{
    int i = blockIdx.x * blockDim.x + threadIdx.x;
    if (i < Bq) g_m[i] = 1.f;
}

// ---------------- LSTM pointwise ------------------------------------------------------
__global__ void lstm_pw_kernel(float* __restrict__ h, float* __restrict__ c,
                               const float* __restrict__ mask)
{
    int i = blockIdx.x * blockDim.x + threadIdx.x;
    if (i >= Bq * Hq) return;
    int b = i / Hq, hh = i % Hq;
    const float* gr = g_g + (size_t)b * H4;
    float gi = gr[hh], gf = gr[Hq + hh], gg = gr[2 * Hq + hh], go = gr[3 * Hq + hh];
    float co = c[i];
    float cn = sigf(gf) * co + sigf(gi) * tanhf(gg);
    float hn = sigf(go) * tanhf(cn);
    if (mask) {
        float mt = mask[b];
        float ho = h[i];
        hn = mt * hn + (1.f - mt) * ho;
        cn = mt * cn + (1.f - mt) * co;
    }
    h[i] = hn;
    c[i] = cn;
}

// ---------------- generator head: 8 batches per block, outW reused ---------------------
__global__ __launch_bounds__(256) void gen_out_kernel(const float* __restrict__ outW,
                                                      const float* __restrict__ outb, int l)
{
    int b0 = blockIdx.x * 8;
    __shared__ float hs[8][Hq];
    __shared__ float es[8][MVq];
    int tid = threadIdx.x;

    // load h for 8 batches (32 KB)
    const float4* src = (const float4*)(g_h + (size_t)b0 * Hq);
    float4* dst = (float4*)&hs[0][0];
    for (int i = tid; i < 8 * Hq / 4; i += 256) dst[i] = src[i];
    __syncthreads();

    int n = tid & 63;
    int sb = tid >> 6;  // 0..3
    float accs[2];
#pragma unroll
    for (int rep = 0; rep < 2; rep++) {
        int bb = sb + rep * 4;
        float acc = outb[n];
        const float4* wr = (const float4*)(outW + (size_t)n * Hq);
        const float4* hv = (const float4*)&hs[bb][0];
#pragma unroll 8
        for (int kk = 0; kk < Hq / 4; kk++) {
            float4 w4 = wr[kk];
            float4 h4 = hv[kk];
            acc += w4.x * h4.x + w4.y * h4.y + w4.z * h4.z + w4.w * h4.w;
        }
        accs[rep] = acc;
        es[bb][n] = acc;
    }
    __syncthreads();

    float er[2];
#pragma unroll
    for (int rep = 0; rep < 2; rep++) {
        int bb = sb + rep * 4;
        float mx = -1e30f;
#pragma unroll
        for (int i = 0; i < MVq; i++) mx = fmaxf(mx, es[bb][i]);
        er[rep] = expf(accs[rep] - mx);
    }
    __syncthreads();
#pragma unroll
    for (int rep = 0; rep < 2; rep++) { int bb = sb + rep * 4; es[bb][n] = er[rep]; }
    __syncthreads();
#pragma unroll
    for (int rep = 0; rep < 2; rep++) {
        int bb = sb + rep * 4;
        float ssum = 0.f;
#pragma unroll
        for (int i = 0; i < MVq; i++) ssum += es[bb][i];
        float p = er[rep] / ssum;
        int b = b0 + bb;
        g_msg[(size_t)l * Bq * MVq + b * MVq + n] = p;
        if (n == EOS_IDX) {
            float mo = g_m[b];
            g_msgmask[l * Bq + b] = mo;
            g_m[b] = mo * (1.f - p);
        }
    }
}

// ---------------- decoder input gather --------------------------------------------------
__global__ void decin_kernel(const int* __restrict__ target_var,
                             const float* __restrict__ embedding)
{
    long i = (long)blockIdx.x * blockDim.x + threadIdx.x;
    if (i >= (long)Tq * Bq * Hq) return;
    int hh = (int)(i % Hq);
    long tb = i / Hq;
    int b = (int)(tb % Bq);
    int t = (int)(tb / Bq);
    int idx = (t == 0) ? 0 : target_var[(t - 1) * Bq + b];  // SOS_INDEX = 0
    g_dec_in[i] = embedding[(size_t)idx * Hq + hh];
}

// ---------------- host orchestration ----------------------------------------------------
static inline void launch_mma(const float* A, const float* W, float* C,
                              int M, int N, int K,
                              const float* bias, const float* addM, int addN,
                              float* C2 = nullptr, int colSplit = -1,
                              int ldC = -1, int ldC2 = 0)
{
    if (colSplit < 0) colSplit = N;
    if (ldC < 0) ldC = (colSplit < N) ? colSplit : N;
    dim3 grid(N / 128, M / 128);
    mma_gemm_kernel<<<grid, 256>>>(A, W, C, C2, M, N, K, bias, addM, addN,
                                   colSplit, ldC, ldC2);
}

extern "C" void kernel_launch(void* const* d_in, const int* in_sizes, int n_in,
                              void* d_out, int out_size)
{
    int k = 0;
    const int*   input_var  = (const int*)d_in[k++];
    const float* input_mask = (const float*)d_in[k++];
    const int*   target_var = (const int*)d_in[k++];
    if (n_in >= 32) k++;  // skip target_max_len scalar if present
    const float* embedding = (const float*)d_in[k++];
    const float* attn_w    = (const float*)d_in[k++];
    const float* attn_b    = (const float*)d_in[k++];
    const float* set_Wih   = (const float*)d_in[k++];
    const float* set_Whh   = (const float*)d_in[k++];
    const float* set_bih   = (const float*)d_in[k++];
    const float* set_bhh   = (const float*)d_in[k++];
    const float* set_h0    = (const float*)d_in[k++];
    const float* set_c0    = (const float*)d_in[k++];
    const float* gen_x0    = (const float*)d_in[k++];
    const float* gen_Wih   = (const float*)d_in[k++];
    const float* gen_Whh   = (const float*)d_in[k++];
    const float* gen_bih   = (const float*)d_in[k++];
    const float* gen_bhh   = (const float*)d_in[k++];
    const float* gen_outW  = (const float*)d_in[k++];
    const float* gen_outb  = (const float*)d_in[k++];
    const float* menc_Wih  = (const float*)d_in[k++];
    const float* menc_Whh  = (const float*)d_in[k++];
    const float* menc_bih  = (const float*)d_in[k++];
    const float* menc_bhh  = (const float*)d_in[k++];
    const float* menc_h0   = (const float*)d_in[k++];
    const float* menc_c0   = (const float*)d_in[k++];
    const float* dec_Wih   = (const float*)d_in[k++];
    const float* dec_Whh   = (const float*)d_in[k++];
    const float* dec_bih   = (const float*)d_in[k++];
    const float* dec_bhh   = (const float*)d_in[k++];
    const float* dec_outW  = (const float*)d_in[k++];
    const float* dec_outb  = (const float*)d_in[k++];
    float* out = (float*)d_out;

    float *p_r, *p_h, *p_c, *p_g, *p_msg, *p_mm, *p_vec, *p_mx, *p_dx, *p_di, *p_dW, *p_db;
    cudaGetSymbolAddress((void**)&p_r,   g_r);
    cudaGetSymbolAddress((void**)&p_h,   g_h);
    cudaGetSymbolAddress((void**)&p_c,   g_c);
    cudaGetSymbolAddress((void**)&p_g,   g_g);
    cudaGetSymbolAddress((void**)&p_msg, g_msg);
    cudaGetSymbolAddress((void**)&p_mm,  g_msgmask);
    cudaGetSymbolAddress((void**)&p_vec, g_vec);
    cudaGetSymbolAddress((void**)&p_mx,  g_menc_xterm);
    cudaGetSymbolAddress((void**)&p_dx,  g_dec_xterm);
    cudaGetSymbolAddress((void**)&p_di,  g_dec_in);
    cudaGetSymbolAddress((void**)&p_dW,  g_decW);
    cudaGetSymbolAddress((void**)&p_db,  g_decb);

    const int BH = Bq * Hq;

    // build combined decoder weight [Whh; outW] and bias [bhh; outb]
    cudaMemcpyAsync(p_dW, dec_Whh, (size_t)H4 * Hq * 4, cudaMemcpyDeviceToDevice);
    cudaMemcpyAsync(p_dW + (size_t)H4 * Hq, dec_outW, (size_t)Vq * Hq * 4,
                    cudaMemcpyDeviceToDevice);
    cudaMemcpyAsync(p_db, dec_bhh, H4 * 4, cudaMemcpyDeviceToDevice);
    cudaMemcpyAsync(p_db + H4, dec_outb, Vq * 4, cudaMemcpyDeviceToDevice);

    // ===== encoder (set attention + 1 LSTM cell) =====
    cterm_kernel<<<1, 256>>>(set_h0, attn_w, attn_b);
    aw_kernel<<<(Bq * Wq * 32 + 255) / 256, 256>>>(input_var, input_mask, embedding, attn_w);
    r_kernel<<<Bq, 256>>>(input_var, embedding);
    vecgate_kernel<<<(H4 * 32 + 255) / 256, 256>>>(set_h0, set_Whh, set_bih, set_bhh, Hq);
    launch_mma(p_r, set_Wih, p_g, Bq, H4, Hq, p_vec, nullptr, 0);
    bcast_kernel<<<(BH + 255) / 256, 256>>>(p_c, set_c0);
    lstm_pw_kernel<<<(BH + 255) / 256, 256>>>(p_h, p_c, nullptr);

    // ===== generator scan (L steps) =====
    vecgate_kernel<<<(H4 * 32 + 255) / 256, 256>>>(gen_x0, gen_Wih, gen_bih, gen_bhh, MVq);
    ones_kernel<<<(Bq + 255) / 256, 256>>>();
    for (int l = 0; l < Lq; l++) {
        launch_mma(p_h, gen_Whh, p_g, Bq, H4, Hq, p_vec, nullptr, 0);
        lstm_pw_kernel<<<(BH + 255) / 256, 256>>>(p_h, p_c, nullptr);
        gen_out_kernel<<<Bq / 8, 256>>>(gen_outW, gen_outb, l);
    }

    // ===== message encoder: hoisted x-term GEMM, then masked scan =====
    launch_mma(p_msg, menc_Wih, p_mx, Lq * Bq, H4, MVq, menc_bih, nullptr, 0);
    bcast_kernel<<<(BH + 255) / 256, 256>>>(p_h, menc_h0);
    bcast_kernel<<<(BH + 255) / 256, 256>>>(p_c, menc_c0);
    for (int l = 0; l < Lq; l++) {
        launch_mma(p_h, menc_Whh, p_g, Bq, H4, Hq, menc_bhh,
                   p_mx + (size_t)l * Bq * H4, H4);
        lstm_pw_kernel<<<(BH + 255) / 256, 256>>>(p_h, p_c, p_mm + (size_t)l * Bq);
    }

    // ===== decoder =====
    decin_kernel<<<(int)(((long)Tq * Bq * Hq + 255) / 256), 256>>>(target_var, embedding);
    launch_mma(p_di, dec_Wih, p_dx, Tq * Bq, H4, Hq, dec_bih, nullptr, 0);

    // t=0: plain recurrent gemm (no logits yet)
    launch_mma(p_h, dec_Whh, p_g, Bq, H4, Hq, dec_bhh, p_dx, H4);
    lstm_pw_kernel<<<(BH + 255) / 256, 256>>>(p_h, p_c, nullptr);
    // t=1..49: combined [Whh | outW] gemm -> g_t and logits_{t-1}
    for (int t = 1; t < Tq; t++) {
        launch_mma(p_h, p_dW, p_g, Bq, H4 + Vq, Hq, p_db,
                   p_dx + (size_t)t * Bq * H4, H4,
                   out + (size_t)(t - 1) * Bq * Vq, H4, H4, Vq);
        lstm_pw_kernel<<<(BH + 255) / 256, 256>>>(p_h, p_c, nullptr);
    }
    // final logits_{T-1}
    launch_mma(p_h, dec_outW, out + (size_t)(Tq - 1) * Bq * Vq, Bq, Vq, Hq,
               dec_outb, nullptr, 0);
}